// round 3
// baseline (speedup 1.0000x reference)
#include <cuda_runtime.h>

// seq2seq GRU encoder/decoder with attention.
// V=30000, E=256, H=512, B=64, S=64, max_len=32.
// fc logits via tf32x3 split mma.sync (fp32-equivalent precision);
// recurrent state stored transposed [feature][batch] for coalescing.

#define NB 64
#define NS 64
#define NE 256
#define NH 512
#define NH3 1536
#define NV 30000
#define NT 32
#define KC 16

// ---------------- device scratch ----------------
__device__ float g_ex[NB * NS * NE];
__device__ float g_gi[NB * NS * NH3];
__device__ float g_hA[NH * NB];            // transposed [h][b]
__device__ float g_hB[NH * NB];            // transposed [h][b]
__device__ float g_enc[NB * NS * NH];      // [b][s][h]
__device__ float g_temp[NB * NS * NH];
__device__ float g_ctx[NH * NB];           // transposed [h][b]
__device__ float g_demb[NE * NB];          // transposed [e][b]
__device__ unsigned long long g_amax[NB];

__device__ __forceinline__ float sigf(float x) { return 1.0f / (1.0f + expf(-x)); }
__device__ __forceinline__ unsigned f2tf(float x) {
    unsigned u; asm("cvt.rna.tf32.f32 %0, %1;" : "=r"(u) : "f"(x)); return u;
}

// ---------------- embedding + init ----------------
__global__ __launch_bounds__(256) void k_embed(const int* __restrict__ x,
                                               const float* __restrict__ emb) {
    int i = blockIdx.x * 256 + threadIdx.x;
    int bs = i >> 8, e = i & 255;
    g_ex[i] = emb[x[bs] * NE + e];
}

__global__ __launch_bounds__(256) void k_zero_h() {
    int i = blockIdx.x * 256 + threadIdx.x;
    if (i < NH * NB) g_hA[i] = 0.0f;
}

// ---------------- 64x64 SGEMM: C = A @ W^T + bias (gi and temp) ----------------
__global__ __launch_bounds__(256) void k_sgemm64(int sel, const float* __restrict__ W,
                                                 const float* __restrict__ bias,
                                                 int N, int K) {
    const float* A = sel ? g_enc : g_ex;
    float* C = sel ? g_temp : g_gi;
    __shared__ __align__(16) float As[KC][68];
    __shared__ __align__(16) float Ws[KC][68];
    int tid = threadIdx.x;
    int tx = tid & 15, ty = tid >> 4;
    int m0 = blockIdx.y * 64, n0 = blockIdx.x * 64;
    int lr = tid >> 2, lk = (tid & 3) * 4;
    float acc[4][4] = {};
    for (int k0 = 0; k0 < K; k0 += KC) {
        float4 av = *(const float4*)&A[(m0 + lr) * K + k0 + lk];
        float4 wv = *(const float4*)&W[(n0 + lr) * K + k0 + lk];
        __syncthreads();
        As[lk + 0][lr] = av.x; As[lk + 1][lr] = av.y; As[lk + 2][lr] = av.z; As[lk + 3][lr] = av.w;
        Ws[lk + 0][lr] = wv.x; Ws[lk + 1][lr] = wv.y; Ws[lk + 2][lr] = wv.z; Ws[lk + 3][lr] = wv.w;
        __syncthreads();
#pragma unroll
        for (int k = 0; k < KC; k++) {
            float4 a = *(const float4*)&As[k][tx * 4];
            float4 w = *(const float4*)&Ws[k][ty * 4];
            acc[0][0] += a.x * w.x; acc[0][1] += a.x * w.y; acc[0][2] += a.x * w.z; acc[0][3] += a.x * w.w;
            acc[1][0] += a.y * w.x; acc[1][1] += a.y * w.y; acc[1][2] += a.y * w.z; acc[1][3] += a.y * w.w;
            acc[2][0] += a.z * w.x; acc[2][1] += a.z * w.y; acc[2][2] += a.z * w.z; acc[2][3] += a.z * w.w;
            acc[3][0] += a.w * w.x; acc[3][1] += a.w * w.y; acc[3][2] += a.w * w.z; acc[3][3] += a.w * w.w;
        }
    }
#pragma unroll
    for (int i = 0; i < 4; i++) {
        int m = m0 + tx * 4 + i;
#pragma unroll
        for (int j = 0; j < 4; j++) {
            int n = n0 + ty * 4 + j;
            C[m * N + n] = acc[i][j] + bias[n];
        }
    }
}

// ---------------- encoder GRU step ----------------
// 128 blocks x 4 hidden units. Whole weight slice (12 rows x 512) staged to smem
// once; h streamed from transposed buffer (coalesced), weights via broadcast LDS.128.
__global__ __launch_bounds__(256) void k_enc_step(const float* __restrict__ Whh,
                                                  const float* __restrict__ bhh,
                                                  int t, int swap) {
    const float* hin = swap ? g_hB : g_hA;   // [NH][NB]
    float* hout = swap ? g_hA : g_hB;
    int j0 = blockIdx.x * 4;
    __shared__ __align__(16) float Ws[12][NH];  // row r = gate*4 + jj
    int tid = threadIdx.x;
    // stage weight slice: 12 rows x 512 floats = 1536 float4
    for (int i = tid; i < 12 * (NH / 4); i += 256) {
        int r = i / (NH / 4), c4 = i % (NH / 4);
        int g = r >> 2, jj = r & 3;
        *(float4*)&Ws[r][c4 * 4] = *(const float4*)&Whh[(g * NH + j0 + jj) * NH + c4 * 4];
    }
    __syncthreads();
    int b = tid & 63, jj = tid >> 6;
    float a0 = 0.f, a1 = 0.f, a2 = 0.f;
    float p0 = hin[0 * NB + b], p1 = hin[1 * NB + b], p2 = hin[2 * NB + b], p3 = hin[3 * NB + b];
#pragma unroll 4
    for (int k0 = 0; k0 < NH; k0 += 4) {
        float h0 = p0, h1 = p1, h2 = p2, h3 = p3;
        int kn = k0 + 4;
        if (kn < NH) {
            p0 = hin[(kn + 0) * NB + b]; p1 = hin[(kn + 1) * NB + b];
            p2 = hin[(kn + 2) * NB + b]; p3 = hin[(kn + 3) * NB + b];
        }
        float4 w0 = *(const float4*)&Ws[jj][k0];
        float4 w1 = *(const float4*)&Ws[4 + jj][k0];
        float4 w2 = *(const float4*)&Ws[8 + jj][k0];
        a0 += h0 * w0.x + h1 * w0.y + h2 * w0.z + h3 * w0.w;
        a1 += h0 * w1.x + h1 * w1.y + h2 * w1.z + h3 * w1.w;
        a2 += h0 * w2.x + h1 * w2.y + h2 * w2.z + h3 * w2.w;
    }
    int j = j0 + jj;
    const float* gi = &g_gi[(b * NS + t) * NH3];  // includes bih
    float r = sigf(gi[j] + a0 + bhh[j]);
    float z = sigf(gi[NH + j] + a1 + bhh[NH + j]);
    float n = tanhf(gi[2 * NH + j] + r * (a2 + bhh[2 * NH + j]));
    float hp = hin[j * NB + b];
    float hn = (1.0f - z) * n + z * hp;
    hout[j * NB + b] = hn;
    g_enc[(b * NS + t) * NH + j] = hn;
}

// ---------------- decoder init ----------------
__global__ __launch_bounds__(256) void k_dec_init(const int* __restrict__ sd,
                                                  const float* __restrict__ emb) {
    int b = blockIdx.x, tid = threadIdx.x;
    // ctx (transposed) = h_enc (transposed): flat copy, coalesced
    for (int i = tid; i < NH; i += 256) g_ctx[b * NH + i] = g_hA[b * NH + i];
    int idx = sd[b];
    g_demb[tid * NB + b] = emb[idx * NE + tid];  // tid == e (NE == 256)
    if (tid == 0) g_amax[b] = 0ull;
}

// ---------------- decoder GRU step ----------------
__global__ __launch_bounds__(256) void k_dec_step(const float* __restrict__ Wih,
                                                  const float* __restrict__ Whh,
                                                  const float* __restrict__ bih,
                                                  const float* __restrict__ bhh,
                                                  int swap) {
    const float* hin = swap ? g_hB : g_hA;
    float* hout = swap ? g_hA : g_hB;
    int j0 = blockIdx.x * 4;
    __shared__ __align__(16) float Ws[12][NE + NH];  // 36 KB
    int tid = threadIdx.x;
    int b = tid & 63, jj = tid >> 6;
    const int KI = NE + NH;  // 768
    // phase 1: input gates over [demb | ctx] (transposed sources)
    for (int i = tid; i < 12 * (KI / 4); i += 256) {
        int r = i / (KI / 4), c4 = i % (KI / 4);
        int g = r >> 2, j2 = r & 3;
        *(float4*)&Ws[r][c4 * 4] = *(const float4*)&Wih[(g * NH + j0 + j2) * KI + c4 * 4];
    }
    __syncthreads();
    float ai0 = 0.f, ai1 = 0.f, ai2 = 0.f;
    {
        float p0 = g_demb[0 * NB + b], p1 = g_demb[1 * NB + b],
              p2 = g_demb[2 * NB + b], p3 = g_demb[3 * NB + b];
#pragma unroll 4
        for (int k0 = 0; k0 < KI; k0 += 4) {
            float h0 = p0, h1 = p1, h2 = p2, h3 = p3;
            int kn = k0 + 4;
            if (kn < KI) {
                const float* src = (kn < NE) ? &g_demb[kn * NB] : &g_ctx[(kn - NE) * NB];
                p0 = src[0 * NB + b]; p1 = src[1 * NB + b];
                p2 = src[2 * NB + b]; p3 = src[3 * NB + b];
            }
            float4 w0 = *(const float4*)&Ws[jj][k0];
            float4 w1 = *(const float4*)&Ws[4 + jj][k0];
            float4 w2 = *(const float4*)&Ws[8 + jj][k0];
            ai0 += h0 * w0.x + h1 * w0.y + h2 * w0.z + h3 * w0.w;
            ai1 += h0 * w1.x + h1 * w1.y + h2 * w1.z + h3 * w1.w;
            ai2 += h0 * w2.x + h1 * w2.y + h2 * w2.z + h3 * w2.w;
        }
    }
    __syncthreads();
    // phase 2: hidden gates
    for (int i = tid; i < 12 * (NH / 4); i += 256) {
        int r = i / (NH / 4), c4 = i % (NH / 4);
        int g = r >> 2, j2 = r & 3;
        *(float4*)&Ws[r][c4 * 4] = *(const float4*)&Whh[(g * NH + j0 + j2) * NH + c4 * 4];
    }
    __syncthreads();
    float ah0 = 0.f, ah1 = 0.f, ah2 = 0.f;
    {
        float p0 = hin[0 * NB + b], p1 = hin[1 * NB + b],
              p2 = hin[2 * NB + b], p3 = hin[3 * NB + b];
#pragma unroll 4
        for (int k0 = 0; k0 < NH; k0 += 4) {
            float h0 = p0, h1 = p1, h2 = p2, h3 = p3;
            int kn = k0 + 4;
            if (kn < NH) {
                p0 = hin[(kn + 0) * NB + b]; p1 = hin[(kn + 1) * NB + b];
                p2 = hin[(kn + 2) * NB + b]; p3 = hin[(kn + 3) * NB + b];
            }
            float4 w0 = *(const float4*)&Ws[jj][k0];
            float4 w1 = *(const float4*)&Ws[4 + jj][k0];
            float4 w2 = *(const float4*)&Ws[8 + jj][k0];
            ah0 += h0 * w0.x + h1 * w0.y + h2 * w0.z + h3 * w0.w;
            ah1 += h0 * w1.x + h1 * w1.y + h2 * w1.z + h3 * w1.w;
            ah2 += h0 * w2.x + h1 * w2.y + h2 * w2.z + h3 * w2.w;
        }
    }
    int j = j0 + jj;
    float r = sigf(ai0 + bih[j] + ah0 + bhh[j]);
    float z = sigf(ai1 + bih[NH + j] + ah1 + bhh[NH + j]);
    float n = tanhf(ai2 + bih[2 * NH + j] + r * (ah2 + bhh[2 * NH + j]));
    float hp = hin[j * NB + b];
    hout[j * NB + b] = (1.0f - z) * n + z * hp;
}

// ---------------- fc logits via tf32x3 mma + argmax ----------------
// score = [h | ctx] @ fc_W^T + fc_b.  M=64 (batch), N tile=128, K=1024, KB=16.
// Each fp32 operand split into tf32 hi/lo; 3 cross products accumulated in fp32.
#define MMA8(C, A, B0, B1)                                                        \
    asm volatile("mma.sync.aligned.m16n8k8.row.col.f32.tf32.tf32.f32 "            \
                 "{%0,%1,%2,%3},{%4,%5,%6,%7},{%8,%9},{%0,%1,%2,%3};"             \
                 : "+f"(C[0]), "+f"(C[1]), "+f"(C[2]), "+f"(C[3])                 \
                 : "r"(A[0]), "r"(A[1]), "r"(A[2]), "r"(A[3]), "r"(B0), "r"(B1))

__global__ __launch_bounds__(256, 2) void k_fc(const float* __restrict__ fcW,
                                               const float* __restrict__ fcb,
                                               float* __restrict__ out,
                                               int step, int swap) {
    const float* hT = swap ? g_hA : g_hB;   // [NH][NB]
    __shared__ unsigned As_hi[16][68], As_lo[16][68];
    __shared__ unsigned Bs_hi[128][20], Bs_lo[128][20];
    __shared__ unsigned long long best[64];
    int tid = threadIdx.x;
    int lane = tid & 31, wid = tid >> 5;
    int warp_m = wid & 1, warp_n = wid >> 1;
    int gid = lane >> 2, tig = lane & 3;
    int v0 = blockIdx.x * 128;
    if (tid < 64) best[tid] = 0ull;

    // per-thread global-load coords
    int akk = tid >> 4, am4 = (tid & 15) * 4;              // A: [k][m4..m4+3]
    int bn0 = (tid * 2) >> 2, bk0 = ((tid * 2) & 3) * 4;   // B: two float4
    int bn1 = (tid * 2 + 1) >> 2, bk1 = ((tid * 2 + 1) & 3) * 4;
    bool ok0 = (v0 + bn0) < NV, ok1 = (v0 + bn1) < NV;

    float4 aR, bR0, bR1;
    const float4 z4 = make_float4(0.f, 0.f, 0.f, 0.f);

    // load chunk 0
    {
        int k0 = 0;
        aR = *(const float4*)&hT[(k0 + akk) * NB + am4];
        bR0 = ok0 ? *(const float4*)&fcW[(v0 + bn0) * (2 * NH) + k0 + bk0] : z4;
        bR1 = ok1 ? *(const float4*)&fcW[(v0 + bn1) * (2 * NH) + k0 + bk1] : z4;
    }
    float cacc[2][4][4] = {};

    for (int c = 0; c < 64; c++) {
        // convert + store current chunk regs to smem
        {
            float av[4] = {aR.x, aR.y, aR.z, aR.w};
#pragma unroll
            for (int i = 0; i < 4; i++) {
                unsigned hb = f2tf(av[i]);
                As_hi[akk][am4 + i] = hb;
                As_lo[akk][am4 + i] = f2tf(av[i] - __uint_as_float(hb));
            }
            float bv0[4] = {bR0.x, bR0.y, bR0.z, bR0.w};
            float bv1[4] = {bR1.x, bR1.y, bR1.z, bR1.w};
#pragma unroll
            for (int i = 0; i < 4; i++) {
                unsigned hb = f2tf(bv0[i]);
                Bs_hi[bn0][bk0 + i] = hb;
                Bs_lo[bn0][bk0 + i] = f2tf(bv0[i] - __uint_as_float(hb));
            }
#pragma unroll
            for (int i = 0; i < 4; i++) {
                unsigned hb = f2tf(bv1[i]);
                Bs_hi[bn1][bk1 + i] = hb;
                Bs_lo[bn1][bk1 + i] = f2tf(bv1[i] - __uint_as_float(hb));
            }
        }
        __syncthreads();
        // prefetch next chunk
        if (c + 1 < 64) {
            int k0 = (c + 1) * KC;
            const float* asrc = (k0 < NH) ? &hT[(k0 + akk) * NB + am4]
                                          : &g_ctx[(k0 - NH + akk) * NB + am4];
            aR = *(const float4*)asrc;
            bR0 = ok0 ? *(const float4*)&fcW[(v0 + bn0) * (2 * NH) + k0 + bk0] : z4;
            bR1 = ok1 ? *(const float4*)&fcW[(v0 + bn1) * (2 * NH) + k0 + bk1] : z4;
        }
        // mma over the chunk (2 x k8)
#pragma unroll
        for (int s = 0; s < 2; s++) {
            int kl = s * 8;
            unsigned ah[2][4], al[2][4];
#pragma unroll
            for (int mt = 0; mt < 2; mt++) {
                int r0 = warp_m * 32 + mt * 16 + gid;
                ah[mt][0] = As_hi[kl + tig][r0];     ah[mt][1] = As_hi[kl + tig][r0 + 8];
                ah[mt][2] = As_hi[kl + tig + 4][r0]; ah[mt][3] = As_hi[kl + tig + 4][r0 + 8];
                al[mt][0] = As_lo[kl + tig][r0];     al[mt][1] = As_lo[kl + tig][r0 + 8];
                al[mt][2] = As_lo[kl + tig + 4][r0]; al[mt][3] = As_lo[kl + tig + 4][r0 + 8];
            }
#pragma unroll
            for (int nt = 0; nt < 4; nt++) {
                int cb = warp_n * 32 + nt * 8 + gid;
                unsigned bh0 = Bs_hi[cb][kl + tig], bh1 = Bs_hi[cb][kl + tig + 4];
                unsigned bl0 = Bs_lo[cb][kl + tig], bl1 = Bs_lo[cb][kl + tig + 4];
#pragma unroll
                for (int mt = 0; mt < 2; mt++) {
                    MMA8(cacc[mt][nt], ah[mt], bh0, bh1);
                    MMA8(cacc[mt][nt], ah[mt], bl0, bl1);
                    MMA8(cacc[mt][nt], al[mt], bh0, bh1);
                }
            }
        }
        __syncthreads();
    }

    // epilogue: bias, store, argmax
#pragma unroll
    for (int mt = 0; mt < 2; mt++) {
        int r0 = warp_m * 32 + mt * 16 + gid;
        int r1 = r0 + 8;
        unsigned long long pk0 = 0ull, pk1 = 0ull;
#pragma unroll
        for (int nt = 0; nt < 4; nt++) {
            int col = v0 + warp_n * 32 + nt * 8 + tig * 2;
            if (col < NV) {
                float bsv0 = fcb[col], bsv1 = fcb[col + 1];
                float v00 = cacc[mt][nt][0] + bsv0;
                float v01 = cacc[mt][nt][1] + bsv1;
                float v10 = cacc[mt][nt][2] + bsv0;
                float v11 = cacc[mt][nt][3] + bsv1;
                out[((long long)(r0 * NT + step)) * NV + col] = v00;
                out[((long long)(r0 * NT + step)) * NV + col + 1] = v01;
                out[((long long)(r1 * NT + step)) * NV + col] = v10;
                out[((long long)(r1 * NT + step)) * NV + col + 1] = v11;
                unsigned u;
                u = __float_as_uint(v00); u = (u & 0x80000000u) ? ~u : (u | 0x80000000u);
                { unsigned long long p = ((unsigned long long)u << 32) | (0xFFFFFFFFu - (unsigned)col); if (p > pk0) pk0 = p; }
                u = __float_as_uint(v01); u = (u & 0x80000000u) ? ~u : (u | 0x80000000u);
                { unsigned long long p = ((unsigned long long)u << 32) | (0xFFFFFFFFu - (unsigned)(col + 1)); if (p > pk0) pk0 = p; }
                u = __float_as_uint(v10); u = (u & 0x80000000u) ? ~u : (u | 0x80000000u);
                { unsigned long long p = ((unsigned long long)u << 32) | (0xFFFFFFFFu - (unsigned)col); if (p > pk1) pk1 = p; }
                u = __float_as_uint(v11); u = (u & 0x80000000u) ? ~u : (u | 0x80000000u);
                { unsigned long long p = ((unsigned long long)u << 32) | (0xFFFFFFFFu - (unsigned)(col + 1)); if (p > pk1) pk1 = p; }
            }
        }
        if (pk0) atomicMax(&best[r0], pk0);
        if (pk1) atomicMax(&best[r1], pk1);
    }
    __syncthreads();
    if (tid < 64) atomicMax(&g_amax[tid], best[tid]);
}

// ---------------- attention + next-token embedding + argmax reset ----------------
__global__ __launch_bounds__(256) void k_attn(const float* __restrict__ emb, int swap) {
    int b = blockIdx.x, tid = threadIdx.x;
    const float* hT = swap ? g_hA : g_hB;
    __shared__ float hc[NH];
    __shared__ float sc[NS];
    for (int k = tid; k < NH; k += 256) hc[k] = hT[k * NB + b];
    unsigned long long key = g_amax[b];  // all threads read before reset
    int idx = (int)(0xFFFFFFFFu - (unsigned)(key & 0xFFFFFFFFull));
    for (int e = tid; e < NE; e += 256) g_demb[e * NB + b] = emb[idx * NE + e];
    __syncthreads();
    int w = tid >> 5, lane = tid & 31;
    for (int s = w; s < NS; s += 8) {
        const float* tp = &g_temp[(b * NS + s) * NH];
        float d = 0.f;
        for (int k = lane; k < NH; k += 32) d += tp[k] * hc[k];
#pragma unroll
        for (int off = 16; off; off >>= 1) d += __shfl_down_sync(0xFFFFFFFFu, d, off);
        if (lane == 0) sc[s] = d;
    }
    __syncthreads();
    if (tid == 0) {
        float m = sc[0];
        for (int s = 1; s < NS; s++) m = fmaxf(m, sc[s]);
        float sum = 0.f;
        for (int s = 0; s < NS; s++) { float e2 = expf(sc[s] - m); sc[s] = e2; sum += e2; }
        float inv = 1.0f / sum;
        for (int s = 0; s < NS; s++) sc[s] *= inv;
        g_amax[b] = 0ull;
    }
    __syncthreads();
    for (int hh = tid; hh < NH; hh += 256) {
        float cv = 0.f;
        for (int s = 0; s < NS; s++) cv += sc[s] * g_enc[(b * NS + s) * NH + hh];
        g_ctx[hh * NB + b] = cv;
    }
}

// ---------------- launch ----------------
extern "C" void kernel_launch(void* const* d_in, const int* in_sizes, int n_in,
                              void* d_out, int out_size) {
    const int* x = (const int*)d_in[0];
    const int* sd = (const int*)d_in[1];
    const float* emb = (const float*)d_in[3];
    const float* eWih = (const float*)d_in[4];
    const float* eWhh = (const float*)d_in[5];
    const float* ebih = (const float*)d_in[6];
    const float* ebhh = (const float*)d_in[7];
    const float* dWih = (const float*)d_in[8];
    const float* dWhh = (const float*)d_in[9];
    const float* dbih = (const float*)d_in[10];
    const float* dbhh = (const float*)d_in[11];
    const float* fcW = (const float*)d_in[12];
    const float* fcb = (const float*)d_in[13];
    const float* aW = (const float*)d_in[14];
    const float* ab = (const float*)d_in[15];
    float* out = (float*)d_out;

    k_embed<<<(NB * NS * NE) / 256, 256>>>(x, emb);
    k_zero_h<<<(NH * NB + 255) / 256, 256>>>();

    k_sgemm64<<<dim3(NH3 / 64, (NB * NS) / 64), 256>>>(0, eWih, ebih, NH3, NE);

    for (int t = 0; t < NS; t++)
        k_enc_step<<<NH / 4, 256>>>(eWhh, ebhh, t, t & 1);

    k_sgemm64<<<dim3(NH / 64, (NB * NS) / 64), 256>>>(1, aW, ab, NH, NH);

    k_dec_init<<<NB, 256>>>(sd, emb);

    for (int d = 0; d < NT; d++) {
        int sw = d & 1;
        k_dec_step<<<NH / 4, 256>>>(dWih, dWhh, dbih, dbhh, sw);
        k_fc<<<(NV + 127) / 128, 256>>>(fcW, fcb, out, d, sw);
        k_attn<<<NB, 256>>>(emb, sw);
    }
}

// round 8
// speedup vs baseline: 1.0974x; 1.0974x over previous
#include <cuda_runtime.h>

// seq2seq GRU encoder/decoder with attention.
// V=30000, E=256, H=512, B=64, S=64, max_len=32.
// Encoder: single persistent kernel with software grid barrier.
// fc logits: tf32x3 split mma.sync with fcW pre-converted ONCE to hi/lo.

#define NB 64
#define NS 64
#define NE 256
#define NH 512
#define NH3 1536
#define NV 30000
#define NT 32
#define KC 16
#define ENC_BLOCKS 128

// ---------------- device scratch ----------------
__device__ float g_ex[NB * NS * NE];
__device__ float g_gi[NB * NS * NH3];
__device__ float g_hA[NH * NB];            // transposed [h][b]
__device__ float g_hB[NH * NB];            // transposed [h][b]
__device__ float g_enc[NB * NS * NH];      // [b][s][h]
__device__ float g_temp[NB * NS * NH];
__device__ float g_ctx[NH * NB];           // transposed [h][b]
__device__ float g_demb[NE * NB];          // transposed [e][b]
__device__ unsigned long long g_amax[NB];
__device__ int g_cnt[NS];                  // encoder barrier counters
__device__ unsigned g_fwhi[NV * 2 * NH];   // fcW tf32 hi (122.9 MB)
__device__ unsigned g_fwlo[NV * 2 * NH];   // fcW tf32 lo (122.9 MB)

__device__ __forceinline__ float sigf(float x) { return 1.0f / (1.0f + expf(-x)); }
__device__ __forceinline__ unsigned f2tf(float x) {
    unsigned u; asm("cvt.rna.tf32.f32 %0, %1;" : "=r"(u) : "f"(x)); return u;
}

// ---------------- embedding + init ----------------
__global__ __launch_bounds__(256) void k_embed(const int* __restrict__ x,
                                               const float* __restrict__ emb) {
    int i = blockIdx.x * 256 + threadIdx.x;
    int bs = i >> 8, e = i & 255;
    g_ex[i] = emb[x[bs] * NE + e];
}

__global__ __launch_bounds__(256) void k_zero_h() {
    int i = blockIdx.x * 256 + threadIdx.x;
    if (i < NH * NB) g_hA[i] = 0.0f;
    if (i < NS) g_cnt[i] = 0;
}

// ---------------- fcW -> tf32 hi/lo, once per launch ----------------
__global__ __launch_bounds__(256) void k_conv_fcw(const float* __restrict__ fcW) {
    int i = blockIdx.x * 256 + threadIdx.x;
    if (i < NV * 2 * NH) {
        float x = fcW[i];
        unsigned hb = f2tf(x);
        g_fwhi[i] = hb;
        g_fwlo[i] = f2tf(x - __uint_as_float(hb));
    }
}

// ---------------- 64x64 SGEMM: C = A @ W^T + bias (gi and temp) ----------------
__global__ __launch_bounds__(256) void k_sgemm64(int sel, const float* __restrict__ W,
                                                 const float* __restrict__ bias,
                                                 int N, int K) {
    const float* A = sel ? g_enc : g_ex;
    float* C = sel ? g_temp : g_gi;
    __shared__ __align__(16) float As[KC][68];
    __shared__ __align__(16) float Ws[KC][68];
    int tid = threadIdx.x;
    int tx = tid & 15, ty = tid >> 4;
    int m0 = blockIdx.y * 64, n0 = blockIdx.x * 64;
    int lr = tid >> 2, lk = (tid & 3) * 4;
    float acc[4][4] = {};
    for (int k0 = 0; k0 < K; k0 += KC) {
        float4 av = *(const float4*)&A[(m0 + lr) * K + k0 + lk];
        float4 wv = *(const float4*)&W[(n0 + lr) * K + k0 + lk];
        __syncthreads();
        As[lk + 0][lr] = av.x; As[lk + 1][lr] = av.y; As[lk + 2][lr] = av.z; As[lk + 3][lr] = av.w;
        Ws[lk + 0][lr] = wv.x; Ws[lk + 1][lr] = wv.y; Ws[lk + 2][lr] = wv.z; Ws[lk + 3][lr] = wv.w;
        __syncthreads();
#pragma unroll
        for (int k = 0; k < KC; k++) {
            float4 a = *(const float4*)&As[k][tx * 4];
            float4 w = *(const float4*)&Ws[k][ty * 4];
            acc[0][0] += a.x * w.x; acc[0][1] += a.x * w.y; acc[0][2] += a.x * w.z; acc[0][3] += a.x * w.w;
            acc[1][0] += a.y * w.x; acc[1][1] += a.y * w.y; acc[1][2] += a.y * w.z; acc[1][3] += a.y * w.w;
            acc[2][0] += a.z * w.x; acc[2][1] += a.z * w.y; acc[2][2] += a.z * w.z; acc[2][3] += a.z * w.w;
            acc[3][0] += a.w * w.x; acc[3][1] += a.w * w.y; acc[3][2] += a.w * w.z; acc[3][3] += a.w * w.w;
        }
    }
#pragma unroll
    for (int i = 0; i < 4; i++) {
        int m = m0 + tx * 4 + i;
#pragma unroll
        for (int j = 0; j < 4; j++) {
            int n = n0 + ty * 4 + j;
            C[m * N + n] = acc[i][j] + bias[n];
        }
    }
}

// ---------------- persistent encoder: all 64 GRU steps in one kernel ----------------
__global__ __launch_bounds__(256) void k_enc_persist(const float* __restrict__ Whh,
                                                     const float* __restrict__ bhh) {
    __shared__ __align__(16) float Ws[12][NH];  // 24 KB
    int tid = threadIdx.x;
    int j0 = blockIdx.x * 4;
    for (int i = tid; i < 12 * (NH / 4); i += 256) {
        int r = i / (NH / 4), c4 = i % (NH / 4);
        int g = r >> 2, jj = r & 3;
        *(float4*)&Ws[r][c4 * 4] = *(const float4*)&Whh[(g * NH + j0 + jj) * NH + c4 * 4];
    }
    int b = tid & 63, jj = tid >> 6;
    int j = j0 + jj;
    float bh0 = bhh[j], bh1 = bhh[NH + j], bh2 = bhh[2 * NH + j];
    __syncthreads();

    for (int t = 0; t < NS; t++) {
        const float* hin = (t & 1) ? g_hB : g_hA;
        float* hout = (t & 1) ? g_hA : g_hB;
        float hp = __ldcg(&hin[j * NB + b]);
        float a0 = 0.f, a1 = 0.f, a2 = 0.f;
        float pf[8];
#pragma unroll
        for (int i = 0; i < 8; i++) pf[i] = __ldcg(&hin[i * NB + b]);
        for (int k0 = 0; k0 < NH; k0 += 8) {
            float cur[8];
#pragma unroll
            for (int i = 0; i < 8; i++) cur[i] = pf[i];
            if (k0 + 8 < NH) {
#pragma unroll
                for (int i = 0; i < 8; i++) pf[i] = __ldcg(&hin[(k0 + 8 + i) * NB + b]);
            }
#pragma unroll
            for (int q = 0; q < 8; q += 4) {
                float4 w0 = *(const float4*)&Ws[jj][k0 + q];
                float4 w1 = *(const float4*)&Ws[4 + jj][k0 + q];
                float4 w2 = *(const float4*)&Ws[8 + jj][k0 + q];
                a0 += cur[q] * w0.x + cur[q + 1] * w0.y + cur[q + 2] * w0.z + cur[q + 3] * w0.w;
                a1 += cur[q] * w1.x + cur[q + 1] * w1.y + cur[q + 2] * w1.z + cur[q + 3] * w1.w;
                a2 += cur[q] * w2.x + cur[q + 1] * w2.y + cur[q + 2] * w2.z + cur[q + 3] * w2.w;
            }
        }
        const float* gi = &g_gi[(b * NS + t) * NH3];  // includes bih
        float r = sigf(gi[j] + a0 + bh0);
        float z = sigf(gi[NH + j] + a1 + bh1);
        float n = tanhf(gi[2 * NH + j] + r * (a2 + bh2));
        float hn = (1.0f - z) * n + z * hp;
        hout[j * NB + b] = hn;
        g_enc[(b * NS + t) * NH + j] = hn;

        // grid barrier for step t
        __syncthreads();
        if (tid == 0) {
            __threadfence();
            atomicAdd(&g_cnt[t], 1);
            while (*(volatile int*)&g_cnt[t] < ENC_BLOCKS) {}
            __threadfence();
        }
        __syncthreads();
    }
}

// ---------------- decoder init ----------------
__global__ __launch_bounds__(256) void k_dec_init(const int* __restrict__ sd,
                                                  const float* __restrict__ emb) {
    int b = blockIdx.x, tid = threadIdx.x;
    for (int i = tid; i < NH; i += 256) g_ctx[b * NH + i] = g_hA[b * NH + i];
    int idx = sd[b];
    g_demb[tid * NB + b] = emb[idx * NE + tid];  // tid == e (NE == 256)
    if (tid == 0) g_amax[b] = 0ull;
}

// ---------------- decoder GRU step ----------------
__global__ __launch_bounds__(256) void k_dec_step(const float* __restrict__ Wih,
                                                  const float* __restrict__ Whh,
                                                  const float* __restrict__ bih,
                                                  const float* __restrict__ bhh,
                                                  int swap) {
    const float* hin = swap ? g_hB : g_hA;
    float* hout = swap ? g_hA : g_hB;
    int j0 = blockIdx.x * 4;
    __shared__ __align__(16) float Ws[12][NE + NH];  // 36 KB
    int tid = threadIdx.x;
    int b = tid & 63, jj = tid >> 6;
    const int KI = NE + NH;  // 768
    for (int i = tid; i < 12 * (KI / 4); i += 256) {
        int r = i / (KI / 4), c4 = i % (KI / 4);
        int g = r >> 2, j2 = r & 3;
        *(float4*)&Ws[r][c4 * 4] = *(const float4*)&Wih[(g * NH + j0 + j2) * KI + c4 * 4];
    }
    __syncthreads();
    float ai0 = 0.f, ai1 = 0.f, ai2 = 0.f;
    {
        float pf[8];
#pragma unroll
        for (int i = 0; i < 8; i++) pf[i] = g_demb[i * NB + b];
        for (int k0 = 0; k0 < KI; k0 += 8) {
            float cur[8];
#pragma unroll
            for (int i = 0; i < 8; i++) cur[i] = pf[i];
            int kn = k0 + 8;
            if (kn < KI) {
#pragma unroll
                for (int i = 0; i < 8; i++) {
                    int k = kn + i;
                    const float* s = (k < NE) ? &g_demb[k * NB] : &g_ctx[(k - NE) * NB];
                    pf[i] = s[b];
                }
            }
#pragma unroll
            for (int q = 0; q < 8; q += 4) {
                float4 w0 = *(const float4*)&Ws[jj][k0 + q];
                float4 w1 = *(const float4*)&Ws[4 + jj][k0 + q];
                float4 w2 = *(const float4*)&Ws[8 + jj][k0 + q];
                ai0 += cur[q] * w0.x + cur[q + 1] * w0.y + cur[q + 2] * w0.z + cur[q + 3] * w0.w;
                ai1 += cur[q] * w1.x + cur[q + 1] * w1.y + cur[q + 2] * w1.z + cur[q + 3] * w1.w;
                ai2 += cur[q] * w2.x + cur[q + 1] * w2.y + cur[q + 2] * w2.z + cur[q + 3] * w2.w;
            }
        }
    }
    __syncthreads();
    for (int i = tid; i < 12 * (NH / 4); i += 256) {
        int r = i / (NH / 4), c4 = i % (NH / 4);
        int g = r >> 2, j2 = r & 3;
        *(float4*)&Ws[r][c4 * 4] = *(const float4*)&Whh[(g * NH + j0 + j2) * NH + c4 * 4];
    }
    __syncthreads();
    float ah0 = 0.f, ah1 = 0.f, ah2 = 0.f;
    {
        float pf[8];
#pragma unroll
        for (int i = 0; i < 8; i++) pf[i] = hin[i * NB + b];
        for (int k0 = 0; k0 < NH; k0 += 8) {
            float cur[8];
#pragma unroll
            for (int i = 0; i < 8; i++) cur[i] = pf[i];
            if (k0 + 8 < NH) {
#pragma unroll
                for (int i = 0; i < 8; i++) pf[i] = hin[(k0 + 8 + i) * NB + b];
            }
#pragma unroll
            for (int q = 0; q < 8; q += 4) {
                float4 w0 = *(const float4*)&Ws[jj][k0 + q];
                float4 w1 = *(const float4*)&Ws[4 + jj][k0 + q];
                float4 w2 = *(const float4*)&Ws[8 + jj][k0 + q];
                ah0 += cur[q] * w0.x + cur[q + 1] * w0.y + cur[q + 2] * w0.z + cur[q + 3] * w0.w;
                ah1 += cur[q] * w1.x + cur[q + 1] * w1.y + cur[q + 2] * w1.z + cur[q + 3] * w1.w;
                ah2 += cur[q] * w2.x + cur[q + 1] * w2.y + cur[q + 2] * w2.z + cur[q + 3] * w2.w;
            }
        }
    }
    int j = j0 + jj;
    float r = sigf(ai0 + bih[j] + ah0 + bhh[j]);
    float z = sigf(ai1 + bih[NH + j] + ah1 + bhh[NH + j]);
    float n = tanhf(ai2 + bih[2 * NH + j] + r * (ah2 + bhh[2 * NH + j]));
    float hp = hin[j * NB + b];
    hout[j * NB + b] = (1.0f - z) * n + z * hp;
}

// ---------------- fc logits via tf32x3 mma (pre-converted weights) ----------------
#define MMA8(C, A, B0, B1)                                                        \
    asm volatile("mma.sync.aligned.m16n8k8.row.col.f32.tf32.tf32.f32 "            \
                 "{%0,%1,%2,%3},{%4,%5,%6,%7},{%8,%9},{%0,%1,%2,%3};"             \
                 : "+f"(C[0]), "+f"(C[1]), "+f"(C[2]), "+f"(C[3])                 \
                 : "r"(A[0]), "r"(A[1]), "r"(A[2]), "r"(A[3]), "r"(B0), "r"(B1))

__global__ __launch_bounds__(256, 2) void k_fc(const float* __restrict__ fcb,
                                               float* __restrict__ out,
                                               int step, int swap) {
    const float* hT = swap ? g_hA : g_hB;   // [NH][NB]
    __shared__ __align__(16) unsigned As_hi[16][68], As_lo[16][68];
    __shared__ __align__(16) unsigned Bs_hi[128][20], Bs_lo[128][20];
    __shared__ unsigned long long best[64];
    int tid = threadIdx.x;
    int lane = tid & 31, wid = tid >> 5;
    int warp_m = wid & 1, warp_n = wid >> 1;
    int gid = lane >> 2, tig = lane & 3;
    int v0 = blockIdx.x * 128;
    if (tid < 64) best[tid] = 0ull;

    int akk = tid >> 4, am4 = (tid & 15) * 4;              // A: [k][m4..m4+3]
    int bn0 = (tid * 2) >> 2, bk0 = ((tid * 2) & 3) * 4;   // B: two uint4 rows
    int bn1 = (tid * 2 + 1) >> 2, bk1 = ((tid * 2 + 1) & 3) * 4;
    bool ok0 = (v0 + bn0) < NV, ok1 = (v0 + bn1) < NV;
    long long boff0 = (long long)(v0 + bn0) * (2 * NH);
    long long boff1 = (long long)(v0 + bn1) * (2 * NH);

    float4 aR;
    uint4 bh0R, bl0R, bh1R, bl1R;
    const uint4 z4 = make_uint4(0u, 0u, 0u, 0u);

    {
        aR = *(const float4*)&hT[akk * NB + am4];
        bh0R = ok0 ? *(const uint4*)&g_fwhi[boff0 + bk0] : z4;
        bl0R = ok0 ? *(const uint4*)&g_fwlo[boff0 + bk0] : z4;
        bh1R = ok1 ? *(const uint4*)&g_fwhi[boff1 + bk1] : z4;
        bl1R = ok1 ? *(const uint4*)&g_fwlo[boff1 + bk1] : z4;
    }
    float cacc[2][4][4] = {};

    for (int c = 0; c < 64; c++) {
        {
            float av[4] = {aR.x, aR.y, aR.z, aR.w};
#pragma unroll
            for (int i = 0; i < 4; i++) {
                unsigned hb = f2tf(av[i]);
                As_hi[akk][am4 + i] = hb;
                As_lo[akk][am4 + i] = f2tf(av[i] - __uint_as_float(hb));
            }
            *(uint4*)&Bs_hi[bn0][bk0] = bh0R;
            *(uint4*)&Bs_lo[bn0][bk0] = bl0R;
            *(uint4*)&Bs_hi[bn1][bk1] = bh1R;
            *(uint4*)&Bs_lo[bn1][bk1] = bl1R;
        }
        __syncthreads();
        if (c + 1 < 64) {
            int k0 = (c + 1) * KC;
            const float* asrc = (k0 < NH) ? &hT[(k0 + akk) * NB + am4]
                                          : &g_ctx[(k0 - NH + akk) * NB + am4];
            aR = *(const float4*)asrc;
            bh0R = ok0 ? *(const uint4*)&g_fwhi[boff0 + k0 + bk0] : z4;
            bl0R = ok0 ? *(const uint4*)&g_fwlo[boff0 + k0 + bk0] : z4;
            bh1R = ok1 ? *(const uint4*)&g_fwhi[boff1 + k0 + bk1] : z4;
            bl1R = ok1 ? *(const uint4*)&g_fwlo[boff1 + k0 + bk1] : z4;
        }
#pragma unroll
        for (int s = 0; s < 2; s++) {
            int kl = s * 8;
            unsigned ah[2][4], al[2][4];
#pragma unroll
            for (int mt = 0; mt < 2; mt++) {
                int r0 = warp_m * 32 + mt * 16 + gid;
                ah[mt][0] = As_hi[kl + tig][r0];     ah[mt][1] = As_hi[kl + tig][r0 + 8];
                ah[mt][2] = As_hi[kl + tig + 4][r0]; ah[mt][3] = As_hi[kl + tig + 4][r0 + 8];
                al[mt][0] = As_lo[kl + tig][r0];     al[mt][1] = As_lo[kl + tig][r0 + 8];
                al[mt][2] = As_lo[kl + tig + 4][r0]; al[mt][3] = As_lo[kl + tig + 4][r0 + 8];
            }
#pragma unroll
            for (int nt = 0; nt < 4; nt++) {
                int cb = warp_n * 32 + nt * 8 + gid;
                unsigned bh0 = Bs_hi[cb][kl + tig], bh1 = Bs_hi[cb][kl + tig + 4];
                unsigned bl0 = Bs_lo[cb][kl + tig], bl1 = Bs_lo[cb][kl + tig + 4];
#pragma unroll
                for (int mt = 0; mt < 2; mt++) {
                    MMA8(cacc[mt][nt], ah[mt], bh0, bh1);
                    MMA8(cacc[mt][nt], ah[mt], bl0, bl1);
                    MMA8(cacc[mt][nt], al[mt], bh0, bh1);
                }
            }
        }
        __syncthreads();
    }

#pragma unroll
    for (int mt = 0; mt < 2; mt++) {
        int r0 = warp_m * 32 + mt * 16 + gid;
        int r1 = r0 + 8;
        unsigned long long pk0 = 0ull, pk1 = 0ull;
#pragma unroll
        for (int nt = 0; nt < 4; nt++) {
            int col = v0 + warp_n * 32 + nt * 8 + tig * 2;
            if (col < NV) {
                float bsv0 = fcb[col], bsv1 = fcb[col + 1];
                float v00 = cacc[mt][nt][0] + bsv0;
                float v01 = cacc[mt][nt][1] + bsv1;
                float v10 = cacc[mt][nt][2] + bsv0;
                float v11 = cacc[mt][nt][3] + bsv1;
                out[((long long)(r0 * NT + step)) * NV + col] = v00;
                out[((long long)(r0 * NT + step)) * NV + col + 1] = v01;
                out[((long long)(r1 * NT + step)) * NV + col] = v10;
                out[((long long)(r1 * NT + step)) * NV + col + 1] = v11;
                unsigned u;
                u = __float_as_uint(v00); u = (u & 0x80000000u) ? ~u : (u | 0x80000000u);
                { unsigned long long p = ((unsigned long long)u << 32) | (0xFFFFFFFFu - (unsigned)col); if (p > pk0) pk0 = p; }
                u = __float_as_uint(v01); u = (u & 0x80000000u) ? ~u : (u | 0x80000000u);
                { unsigned long long p = ((unsigned long long)u << 32) | (0xFFFFFFFFu - (unsigned)(col + 1)); if (p > pk0) pk0 = p; }
                u = __float_as_uint(v10); u = (u & 0x80000000u) ? ~u : (u | 0x80000000u);
                { unsigned long long p = ((unsigned long long)u << 32) | (0xFFFFFFFFu - (unsigned)col); if (p > pk1) pk1 = p; }
                u = __float_as_uint(v11); u = (u & 0x80000000u) ? ~u : (u | 0x80000000u);
                { unsigned long long p = ((unsigned long long)u << 32) | (0xFFFFFFFFu - (unsigned)(col + 1)); if (p > pk1) pk1 = p; }
            }
        }
        if (pk0) atomicMax(&best[r0], pk0);
        if (pk1) atomicMax(&best[r1], pk1);
    }
    __syncthreads();
    if (tid < 64) atomicMax(&g_amax[tid], best[tid]);
}

// ---------------- attention + next-token embedding + argmax reset ----------------
__global__ __launch_bounds__(256) void k_attn(const float* __restrict__ emb, int swap) {
    int b = blockIdx.x, tid = threadIdx.x;
    const float* hT = swap ? g_hA : g_hB;
    __shared__ float hc[NH];
    __shared__ float sc[NS];
    for (int k = tid; k < NH; k += 256) hc[k] = hT[k * NB + b];
    unsigned long long key = g_amax[b];  // all threads read before reset
    int idx = (int)(0xFFFFFFFFu - (unsigned)(key & 0xFFFFFFFFull));
    for (int e = tid; e < NE; e += 256) g_demb[e * NB + b] = emb[idx * NE + e];
    __syncthreads();
    int w = tid >> 5, lane = tid & 31;
    for (int s = w; s < NS; s += 8) {
        const float* tp = &g_temp[(b * NS + s) * NH];
        float d = 0.f;
        for (int k = lane; k < NH; k += 32) d += tp[k] * hc[k];
#pragma unroll
        for (int off = 16; off; off >>= 1) d += __shfl_down_sync(0xFFFFFFFFu, d, off);
        if (lane == 0) sc[s] = d;
    }
    __syncthreads();
    if (tid == 0) {
        float m = sc[0];
        for (int s = 1; s < NS; s++) m = fmaxf(m, sc[s]);
        float sum = 0.f;
        for (int s = 0; s < NS; s++) { float e2 = expf(sc[s] - m); sc[s] = e2; sum += e2; }
        float inv = 1.0f / sum;
        for (int s = 0; s < NS; s++) sc[s] *= inv;
        g_amax[b] = 0ull;
    }
    __syncthreads();
    for (int hh = tid; hh < NH; hh += 256) {
        float cv = 0.f;
        for (int s = 0; s < NS; s++) cv += sc[s] * g_enc[(b * NS + s) * NH + hh];
        g_ctx[hh * NB + b] = cv;
    }
}

// ---------------- launch ----------------
extern "C" void kernel_launch(void* const* d_in, const int* in_sizes, int n_in,
                              void* d_out, int out_size) {
    const int* x = (const int*)d_in[0];
    const int* sd = (const int*)d_in[1];
    const float* emb = (const float*)d_in[3];
    const float* eWih = (const float*)d_in[4];
    const float* eWhh = (const float*)d_in[5];
    const float* ebih = (const float*)d_in[6];
    const float* ebhh = (const float*)d_in[7];
    const float* dWih = (const float*)d_in[8];
    const float* dWhh = (const float*)d_in[9];
    const float* dbih = (const float*)d_in[10];
    const float* dbhh = (const float*)d_in[11];
    const float* fcW = (const float*)d_in[12];
    const float* fcb = (const float*)d_in[13];
    const float* aW = (const float*)d_in[14];
    const float* ab = (const float*)d_in[15];
    float* out = (float*)d_out;

    k_embed<<<(NB * NS * NE) / 256, 256>>>(x, emb);
    k_zero_h<<<(NH * NB + 255) / 256, 256>>>();        // also zeroes barrier counters
    k_conv_fcw<<<(NV * 2 * NH + 255) / 256, 256>>>(fcW);

    k_sgemm64<<<dim3(NH3 / 64, (NB * NS) / 64), 256>>>(0, eWih, ebih, NH3, NE);

    k_enc_persist<<<ENC_BLOCKS, 256>>>(eWhh, ebhh);    // all 64 steps

    k_sgemm64<<<dim3(NH / 64, (NB * NS) / 64), 256>>>(1, aW, ab, NH, NH);

    k_dec_init<<<NB, 256>>>(sd, emb);

    for (int d = 0; d < NT; d++) {
        int sw = d & 1;
        k_dec_step<<<NH / 4, 256>>>(dWih, dWhh, dbih, dbhh, sw);
        k_fc<<<(NV + 127) / 128, 256>>>(fcb, out, d, sw);
        k_attn<<<NB, 256>>>(emb, sw);
    }
}

// round 15
// speedup vs baseline: 1.2953x; 1.1803x over previous
#include <cuda_runtime.h>

// seq2seq GRU encoder/decoder with attention.
// V=30000, E=256, H=512, B=64, S=64, max_len=32.
// Encoder: persistent kernel with software grid barrier.
// Decoder: 2 launches/step — dec_step (GRU + argmax-feedback gather) and
// fc_attn (tf32x3 mma logits+argmax fused with attention context blocks).

#define NB 64
#define NS 64
#define NE 256
#define NH 512
#define NH3 1536
#define NV 30000
#define NT 32
#define KC 16
#define ENC_BLOCKS 128
#define KI (NE + NH)   // 768

// ---------------- device scratch ----------------
__device__ float g_ex[NB * NS * NE];
__device__ float g_gi[NB * NS * NH3];
__device__ float g_hA[NH * NB];              // transposed [h][b]
__device__ float g_hB[NH * NB];              // transposed [h][b]
__device__ float g_enc[NB * NS * NH];        // [b][s][h]
__device__ float g_temp[NB * NS * NH];
__device__ float g_ctx2[2][NH * NB];         // double-buffered ctx, transposed
__device__ float g_demb[NE * NB];            // step-0 decoder input, transposed
__device__ unsigned long long g_amax2[NT * NB];  // per-step packed argmax
__device__ int g_cnt[NS];                    // encoder barrier counters
__device__ unsigned g_fwhi[NV * 2 * NH];     // fcW tf32 hi
__device__ unsigned g_fwlo[NV * 2 * NH];     // fcW tf32 lo

__device__ __forceinline__ float sigf(float x) { return 1.0f / (1.0f + expf(-x)); }
__device__ __forceinline__ unsigned f2tf(float x) {
    unsigned u; asm("cvt.rna.tf32.f32 %0, %1;" : "=r"(u) : "f"(x)); return u;
}

// ---------------- fused setup: conv fcW + embed + zero state ----------------
// grid covers NV*2*NH exactly (120000 blocks x 256)
__global__ __launch_bounds__(256) void k_setup(const int* __restrict__ x,
                                               const float* __restrict__ emb,
                                               const float* __restrict__ fcW) {
    int i = blockIdx.x * 256 + threadIdx.x;
    float v = fcW[i];
    unsigned hb = f2tf(v);
    g_fwhi[i] = hb;
    g_fwlo[i] = f2tf(v - __uint_as_float(hb));
    if (i < NB * NS * NE) {
        int bs = i >> 8, e = i & 255;
        g_ex[i] = emb[x[bs] * NE + e];
    }
    if (i < NH * NB) g_hA[i] = 0.0f;
    if (i < NT * NB) g_amax2[i] = 0ull;
    if (i < NS) g_cnt[i] = 0;
}

// ---------------- 64x64 SGEMM: C = A @ W^T + bias (gi and temp) ----------------
__global__ __launch_bounds__(256) void k_sgemm64(int sel, const float* __restrict__ W,
                                                 const float* __restrict__ bias,
                                                 int N, int K) {
    const float* A = sel ? g_enc : g_ex;
    float* C = sel ? g_temp : g_gi;
    __shared__ __align__(16) float As[KC][68];
    __shared__ __align__(16) float Ws[KC][68];
    int tid = threadIdx.x;
    int tx = tid & 15, ty = tid >> 4;
    int m0 = blockIdx.y * 64, n0 = blockIdx.x * 64;
    int lr = tid >> 2, lk = (tid & 3) * 4;
    float acc[4][4] = {};
    for (int k0 = 0; k0 < K; k0 += KC) {
        float4 av = *(const float4*)&A[(m0 + lr) * K + k0 + lk];
        float4 wv = *(const float4*)&W[(n0 + lr) * K + k0 + lk];
        __syncthreads();
        As[lk + 0][lr] = av.x; As[lk + 1][lr] = av.y; As[lk + 2][lr] = av.z; As[lk + 3][lr] = av.w;
        Ws[lk + 0][lr] = wv.x; Ws[lk + 1][lr] = wv.y; Ws[lk + 2][lr] = wv.z; Ws[lk + 3][lr] = wv.w;
        __syncthreads();
#pragma unroll
        for (int k = 0; k < KC; k++) {
            float4 a = *(const float4*)&As[k][tx * 4];
            float4 w = *(const float4*)&Ws[k][ty * 4];
            acc[0][0] += a.x * w.x; acc[0][1] += a.x * w.y; acc[0][2] += a.x * w.z; acc[0][3] += a.x * w.w;
            acc[1][0] += a.y * w.x; acc[1][1] += a.y * w.y; acc[1][2] += a.y * w.z; acc[1][3] += a.y * w.w;
            acc[2][0] += a.z * w.x; acc[2][1] += a.z * w.y; acc[2][2] += a.z * w.z; acc[2][3] += a.z * w.w;
            acc[3][0] += a.w * w.x; acc[3][1] += a.w * w.y; acc[3][2] += a.w * w.z; acc[3][3] += a.w * w.w;
        }
    }
#pragma unroll
    for (int i = 0; i < 4; i++) {
        int m = m0 + tx * 4 + i;
#pragma unroll
        for (int j = 0; j < 4; j++) {
            int n = n0 + ty * 4 + j;
            C[m * N + n] = acc[i][j] + bias[n];
        }
    }
}

// ---------------- persistent encoder: all 64 GRU steps in one kernel ----------------
__global__ __launch_bounds__(256) void k_enc_persist(const float* __restrict__ Whh,
                                                     const float* __restrict__ bhh) {
    __shared__ __align__(16) float Ws[12][NH];  // 24 KB
    int tid = threadIdx.x;
    int j0 = blockIdx.x * 4;
    for (int i = tid; i < 12 * (NH / 4); i += 256) {
        int r = i / (NH / 4), c4 = i % (NH / 4);
        int g = r >> 2, jj = r & 3;
        *(float4*)&Ws[r][c4 * 4] = *(const float4*)&Whh[(g * NH + j0 + jj) * NH + c4 * 4];
    }
    int b = tid & 63, jj = tid >> 6;
    int j = j0 + jj;
    float bh0 = bhh[j], bh1 = bhh[NH + j], bh2 = bhh[2 * NH + j];
    __syncthreads();

    for (int t = 0; t < NS; t++) {
        const float* hin = (t & 1) ? g_hB : g_hA;
        float* hout = (t & 1) ? g_hA : g_hB;
        float hp = __ldcg(&hin[j * NB + b]);
        float a0 = 0.f, a1 = 0.f, a2 = 0.f;
        float pf[8];
#pragma unroll
        for (int i = 0; i < 8; i++) pf[i] = __ldcg(&hin[i * NB + b]);
        for (int k0 = 0; k0 < NH; k0 += 8) {
            float cur[8];
#pragma unroll
            for (int i = 0; i < 8; i++) cur[i] = pf[i];
            if (k0 + 8 < NH) {
#pragma unroll
                for (int i = 0; i < 8; i++) pf[i] = __ldcg(&hin[(k0 + 8 + i) * NB + b]);
            }
#pragma unroll
            for (int q = 0; q < 8; q += 4) {
                float4 w0 = *(const float4*)&Ws[jj][k0 + q];
                float4 w1 = *(const float4*)&Ws[4 + jj][k0 + q];
                float4 w2 = *(const float4*)&Ws[8 + jj][k0 + q];
                a0 += cur[q] * w0.x + cur[q + 1] * w0.y + cur[q + 2] * w0.z + cur[q + 3] * w0.w;
                a1 += cur[q] * w1.x + cur[q + 1] * w1.y + cur[q + 2] * w1.z + cur[q + 3] * w1.w;
                a2 += cur[q] * w2.x + cur[q + 1] * w2.y + cur[q + 2] * w2.z + cur[q + 3] * w2.w;
            }
        }
        const float* gi = &g_gi[(b * NS + t) * NH3];  // includes bih
        float r = sigf(gi[j] + a0 + bh0);
        float z = sigf(gi[NH + j] + a1 + bh1);
        float n = tanhf(gi[2 * NH + j] + r * (a2 + bh2));
        float hn = (1.0f - z) * n + z * hp;
        hout[j * NB + b] = hn;
        g_enc[(b * NS + t) * NH + j] = hn;

        __syncthreads();
        if (tid == 0) {
            __threadfence();
            atomicAdd(&g_cnt[t], 1);
            while (*(volatile int*)&g_cnt[t] < ENC_BLOCKS) {}
            __threadfence();
        }
        __syncthreads();
    }
}

// ---------------- decoder init: ctx[0] = h_enc, step-0 dec_emb ----------------
__global__ __launch_bounds__(256) void k_dec_init(const int* __restrict__ sd,
                                                  const float* __restrict__ emb) {
    int b = blockIdx.x, tid = threadIdx.x;
    for (int i = tid; i < NH; i += 256) g_ctx2[0][b * NH + i] = g_hA[b * NH + i];
    int idx = sd[b];
    g_demb[tid * NB + b] = emb[idx * NE + tid];  // tid == e (NE == 256)
}

// ---------------- decoder GRU step (+argmax-feedback embedding gather) ----------------
// 256 blocks x 128 threads; each block owns 2 hidden units for all 64 batches.
__global__ __launch_bounds__(128) void k_dec_step(const float* __restrict__ Wih,
                                                  const float* __restrict__ Whh,
                                                  const float* __restrict__ bih,
                                                  const float* __restrict__ bhh,
                                                  const float* __restrict__ emb,
                                                  int step) {
    int swap = step & 1;
    const float* hin = swap ? g_hB : g_hA;
    float* hout = swap ? g_hA : g_hB;
    const float* ctxc = g_ctx2[swap];
    int tid = threadIdx.x;
    int b = tid & 63, jj = tid >> 6;
    int j0 = blockIdx.x * 2;
    __shared__ __align__(16) float Ws[6][KI];  // 18 KB

    // decoded-token embedding row for this batch (argmax feedback)
    const float* erow = emb;
    if (step > 0) {
        unsigned long long key = g_amax2[(step - 1) * NB + b];
        int idx = (int)(0xFFFFFFFFu - (unsigned)(key & 0xFFFFFFFFull));
        erow = emb + (long long)idx * NE;
    }

    // stage Wih slice: 6 rows x 768
    for (int i = tid; i < 6 * (KI / 4); i += 128) {
        int r = i / (KI / 4), c4 = i % (KI / 4);
        int g = r >> 1, j2 = r & 1;
        *(float4*)&Ws[r][c4 * 4] = *(const float4*)&Wih[(g * NH + j0 + j2) * KI + c4 * 4];
    }
    __syncthreads();
    float ai0 = 0.f, ai1 = 0.f, ai2 = 0.f;
    {
        float pf[8];
#pragma unroll
        for (int i = 0; i < 8; i++)
            pf[i] = (step == 0) ? g_demb[i * NB + b] : __ldg(&erow[i]);
        for (int k0 = 0; k0 < KI; k0 += 8) {
            float cur[8];
#pragma unroll
            for (int i = 0; i < 8; i++) cur[i] = pf[i];
            int kn = k0 + 8;
            if (kn < KI) {
#pragma unroll
                for (int i = 0; i < 8; i++) {
                    int k = kn + i;
                    if (k < NE)
                        pf[i] = (step == 0) ? g_demb[k * NB + b] : __ldg(&erow[k]);
                    else
                        pf[i] = ctxc[(k - NE) * NB + b];
                }
            }
#pragma unroll
            for (int q = 0; q < 8; q += 4) {
                float4 w0 = *(const float4*)&Ws[jj][k0 + q];
                float4 w1 = *(const float4*)&Ws[2 + jj][k0 + q];
                float4 w2 = *(const float4*)&Ws[4 + jj][k0 + q];
                ai0 += cur[q] * w0.x + cur[q + 1] * w0.y + cur[q + 2] * w0.z + cur[q + 3] * w0.w;
                ai1 += cur[q] * w1.x + cur[q + 1] * w1.y + cur[q + 2] * w1.z + cur[q + 3] * w1.w;
                ai2 += cur[q] * w2.x + cur[q + 1] * w2.y + cur[q + 2] * w2.z + cur[q + 3] * w2.w;
            }
        }
    }
    __syncthreads();
    // stage Whh slice: 6 rows x 512
    for (int i = tid; i < 6 * (NH / 4); i += 128) {
        int r = i / (NH / 4), c4 = i % (NH / 4);
        int g = r >> 1, j2 = r & 1;
        *(float4*)&Ws[r][c4 * 4] = *(const float4*)&Whh[(g * NH + j0 + j2) * NH + c4 * 4];
    }
    __syncthreads();
    float ah0 = 0.f, ah1 = 0.f, ah2 = 0.f;
    {
        float pf[8];
#pragma unroll
        for (int i = 0; i < 8; i++) pf[i] = hin[i * NB + b];
        for (int k0 = 0; k0 < NH; k0 += 8) {
            float cur[8];
#pragma unroll
            for (int i = 0; i < 8; i++) cur[i] = pf[i];
            if (k0 + 8 < NH) {
#pragma unroll
                for (int i = 0; i < 8; i++) pf[i] = hin[(k0 + 8 + i) * NB + b];
            }
#pragma unroll
            for (int q = 0; q < 8; q += 4) {
                float4 w0 = *(const float4*)&Ws[jj][k0 + q];
                float4 w1 = *(const float4*)&Ws[2 + jj][k0 + q];
                float4 w2 = *(const float4*)&Ws[4 + jj][k0 + q];
                ah0 += cur[q] * w0.x + cur[q + 1] * w0.y + cur[q + 2] * w0.z + cur[q + 3] * w0.w;
                ah1 += cur[q] * w1.x + cur[q + 1] * w1.y + cur[q + 2] * w1.z + cur[q + 3] * w1.w;
                ah2 += cur[q] * w2.x + cur[q + 1] * w2.y + cur[q + 2] * w2.z + cur[q + 3] * w2.w;
            }
        }
    }
    int j = j0 + jj;
    float r = sigf(ai0 + bih[j] + ah0 + bhh[j]);
    float z = sigf(ai1 + bih[NH + j] + ah1 + bhh[NH + j]);
    float n = tanhf(ai2 + bih[2 * NH + j] + r * (ah2 + bhh[2 * NH + j]));
    float hp = hin[j * NB + b];
    hout[j * NB + b] = (1.0f - z) * n + z * hp;
}

// ---------------- fused fc (tf32x3 mma + argmax) + attention context ----------------
// blocks 0..63: attention (softmax + ctx_next, independent of fc argmax)
// blocks 64..298: fc logits tile (v0 = (bid-64)*128) + per-step argmax atomics
struct FcSm {
    unsigned As_hi[16][68], As_lo[16][68];
    unsigned Bs_hi[128][20], Bs_lo[128][20];
    unsigned long long best[64];
};
struct AtSm { float hc[NH]; float sc[NS]; };
union USm { FcSm f; AtSm a; };

#define MMA8(C, A, B0, B1)                                                        \
    asm volatile("mma.sync.aligned.m16n8k8.row.col.f32.tf32.tf32.f32 "            \
                 "{%0,%1,%2,%3},{%4,%5,%6,%7},{%8,%9},{%0,%1,%2,%3};"             \
                 : "+f"(C[0]), "+f"(C[1]), "+f"(C[2]), "+f"(C[3])                 \
                 : "r"(A[0]), "r"(A[1]), "r"(A[2]), "r"(A[3]), "r"(B0), "r"(B1))

__global__ __launch_bounds__(256, 2) void k_fc_attn(const float* __restrict__ fcb,
                                                    float* __restrict__ out,
                                                    int step) {
    int swap = step & 1;
    const float* hT = swap ? g_hA : g_hB;   // [NH][NB], output of this step's dec_step
    __shared__ __align__(16) USm sm;
    int tid = threadIdx.x;

    if (blockIdx.x < 64) {
        // ---- attention context for NEXT step ----
        int b = blockIdx.x;
        float* hc = sm.a.hc;
        float* sc = sm.a.sc;
        for (int k = tid; k < NH; k += 256) hc[k] = hT[k * NB + b];
        __syncthreads();
        int w = tid >> 5, lane = tid & 31;
        for (int s = w; s < NS; s += 8) {
            const float* tp = &g_temp[(b * NS + s) * NH];
            float d = 0.f;
            for (int k = lane; k < NH; k += 32) d += tp[k] * hc[k];
#pragma unroll
            for (int off = 16; off; off >>= 1) d += __shfl_down_sync(0xFFFFFFFFu, d, off);
            if (lane == 0) sc[s] = d;
        }
        __syncthreads();
        if (tid == 0) {
            float m = sc[0];
            for (int s = 1; s < NS; s++) m = fmaxf(m, sc[s]);
            float sum = 0.f;
            for (int s = 0; s < NS; s++) { float e2 = expf(sc[s] - m); sc[s] = e2; sum += e2; }
            float inv = 1.0f / sum;
            for (int s = 0; s < NS; s++) sc[s] *= inv;
        }
        __syncthreads();
        float* cnxt = g_ctx2[swap ^ 1];
        for (int hh = tid; hh < NH; hh += 256) {
            float cv = 0.f;
            for (int s = 0; s < NS; s++) cv += sc[s] * g_enc[(b * NS + s) * NH + hh];
            cnxt[hh * NB + b] = cv;
        }
        return;
    }

    // ---- fc logits tile ----
    const float* ctxc = g_ctx2[swap];
    int lane = tid & 31, wid = tid >> 5;
    int warp_m = wid & 1, warp_n = wid >> 1;
    int gid = lane >> 2, tig = lane & 3;
    int v0 = (blockIdx.x - 64) * 128;
    if (tid < 64) sm.f.best[tid] = 0ull;

    int akk = tid >> 4, am4 = (tid & 15) * 4;
    int bn0 = (tid * 2) >> 2, bk0 = ((tid * 2) & 3) * 4;
    int bn1 = (tid * 2 + 1) >> 2, bk1 = ((tid * 2 + 1) & 3) * 4;
    bool ok0 = (v0 + bn0) < NV, ok1 = (v0 + bn1) < NV;
    long long boff0 = (long long)(v0 + bn0) * (2 * NH);
    long long boff1 = (long long)(v0 + bn1) * (2 * NH);

    float4 aR;
    uint4 bh0R, bl0R, bh1R, bl1R;
    const uint4 z4 = make_uint4(0u, 0u, 0u, 0u);

    {
        aR = *(const float4*)&hT[akk * NB + am4];
        bh0R = ok0 ? *(const uint4*)&g_fwhi[boff0 + bk0] : z4;
        bl0R = ok0 ? *(const uint4*)&g_fwlo[boff0 + bk0] : z4;
        bh1R = ok1 ? *(const uint4*)&g_fwhi[boff1 + bk1] : z4;
        bl1R = ok1 ? *(const uint4*)&g_fwlo[boff1 + bk1] : z4;
    }
    float cacc[2][4][4] = {};

    for (int c = 0; c < 64; c++) {
        {
            float av[4] = {aR.x, aR.y, aR.z, aR.w};
#pragma unroll
            for (int i = 0; i < 4; i++) {
                unsigned hb = f2tf(av[i]);
                sm.f.As_hi[akk][am4 + i] = hb;
                sm.f.As_lo[akk][am4 + i] = f2tf(av[i] - __uint_as_float(hb));
            }
            *(uint4*)&sm.f.Bs_hi[bn0][bk0] = bh0R;
            *(uint4*)&sm.f.Bs_lo[bn0][bk0] = bl0R;
            *(uint4*)&sm.f.Bs_hi[bn1][bk1] = bh1R;
            *(uint4*)&sm.f.Bs_lo[bn1][bk1] = bl1R;
        }
        __syncthreads();
        if (c + 1 < 64) {
            int k0 = (c + 1) * KC;
            const float* asrc = (k0 < NH) ? &hT[(k0 + akk) * NB + am4]
                                          : &ctxc[(k0 - NH + akk) * NB + am4];
            aR = *(const float4*)asrc;
            bh0R = ok0 ? *(const uint4*)&g_fwhi[boff0 + k0 + bk0] : z4;
            bl0R = ok0 ? *(const uint4*)&g_fwlo[boff0 + k0 + bk0] : z4;
            bh1R = ok1 ? *(const uint4*)&g_fwhi[boff1 + k0 + bk1] : z4;
            bl1R = ok1 ? *(const uint4*)&g_fwlo[boff1 + k0 + bk1] : z4;
        }
#pragma unroll
        for (int s = 0; s < 2; s++) {
            int kl = s * 8;
            unsigned ah[2][4], al[2][4];
#pragma unroll
            for (int mt = 0; mt < 2; mt++) {
                int r0 = warp_m * 32 + mt * 16 + gid;
                ah[mt][0] = sm.f.As_hi[kl + tig][r0];     ah[mt][1] = sm.f.As_hi[kl + tig][r0 + 8];
                ah[mt][2] = sm.f.As_hi[kl + tig + 4][r0]; ah[mt][3] = sm.f.As_hi[kl + tig + 4][r0 + 8];
                al[mt][0] = sm.f.As_lo[kl + tig][r0];     al[mt][1] = sm.f.As_lo[kl + tig][r0 + 8];
                al[mt][2] = sm.f.As_lo[kl + tig + 4][r0]; al[mt][3] = sm.f.As_lo[kl + tig + 4][r0 + 8];
            }
#pragma unroll
            for (int nt = 0; nt < 4; nt++) {
                int cb = warp_n * 32 + nt * 8 + gid;
                unsigned bh0 = sm.f.Bs_hi[cb][kl + tig], bh1 = sm.f.Bs_hi[cb][kl + tig + 4];
                unsigned bl0 = sm.f.Bs_lo[cb][kl + tig], bl1 = sm.f.Bs_lo[cb][kl + tig + 4];
#pragma unroll
                for (int mt = 0; mt < 2; mt++) {
                    MMA8(cacc[mt][nt], ah[mt], bh0, bh1);
                    MMA8(cacc[mt][nt], ah[mt], bl0, bl1);
                    MMA8(cacc[mt][nt], al[mt], bh0, bh1);
                }
            }
        }
        __syncthreads();
    }

#pragma unroll
    for (int mt = 0; mt < 2; mt++) {
        int r0 = warp_m * 32 + mt * 16 + gid;
        int r1 = r0 + 8;
        unsigned long long pk0 = 0ull, pk1 = 0ull;
#pragma unroll
        for (int nt = 0; nt < 4; nt++) {
            int col = v0 + warp_n * 32 + nt * 8 + tig * 2;
            if (col < NV) {
                float bsv0 = fcb[col], bsv1 = fcb[col + 1];
                float v00 = cacc[mt][nt][0] + bsv0;
                float v01 = cacc[mt][nt][1] + bsv1;
                float v10 = cacc[mt][nt][2] + bsv0;
                float v11 = cacc[mt][nt][3] + bsv1;
                out[((long long)(r0 * NT + step)) * NV + col] = v00;
                out[((long long)(r0 * NT + step)) * NV + col + 1] = v01;
                out[((long long)(r1 * NT + step)) * NV + col] = v10;
                out[((long long)(r1 * NT + step)) * NV + col + 1] = v11;
                unsigned u;
                u = __float_as_uint(v00); u = (u & 0x80000000u) ? ~u : (u | 0x80000000u);
                { unsigned long long p = ((unsigned long long)u << 32) | (0xFFFFFFFFu - (unsigned)col); if (p > pk0) pk0 = p; }
                u = __float_as_uint(v01); u = (u & 0x80000000u) ? ~u : (u | 0x80000000u);
                { unsigned long long p = ((unsigned long long)u << 32) | (0xFFFFFFFFu - (unsigned)(col + 1)); if (p > pk0) pk0 = p; }
                u = __float_as_uint(v10); u = (u & 0x80000000u) ? ~u : (u | 0x80000000u);
                { unsigned long long p = ((unsigned long long)u << 32) | (0xFFFFFFFFu - (unsigned)col); if (p > pk1) pk1 = p; }
                u = __float_as_uint(v11); u = (u & 0x80000000u) ? ~u : (u | 0x80000000u);
                { unsigned long long p = ((unsigned long long)u << 32) | (0xFFFFFFFFu - (unsigned)(col + 1)); if (p > pk1) pk1 = p; }
            }
        }
        if (pk0) atomicMax(&sm.f.best[r0], pk0);
        if (pk1) atomicMax(&sm.f.best[r1], pk1);
    }
    __syncthreads();
    if (tid < 64) atomicMax(&g_amax2[step * NB + tid], sm.f.best[tid]);
}

// ---------------- launch ----------------
extern "C" void kernel_launch(void* const* d_in, const int* in_sizes, int n_in,
                              void* d_out, int out_size) {
    const int* x = (const int*)d_in[0];
    const int* sd = (const int*)d_in[1];
    const float* emb = (const float*)d_in[3];
    const float* eWih = (const float*)d_in[4];
    const float* eWhh = (const float*)d_in[5];
    const float* ebih = (const float*)d_in[6];
    const float* ebhh = (const float*)d_in[7];
    const float* dWih = (const float*)d_in[8];
    const float* dWhh = (const float*)d_in[9];
    const float* dbih = (const float*)d_in[10];
    const float* dbhh = (const float*)d_in[11];
    const float* fcW = (const float*)d_in[12];
    const float* fcb = (const float*)d_in[13];
    const float* aW = (const float*)d_in[14];
    const float* ab = (const float*)d_in[15];
    float* out = (float*)d_out;

    k_setup<<<(NV * 2 * NH) / 256, 256>>>(x, emb, fcW);

    k_sgemm64<<<dim3(NH3 / 64, (NB * NS) / 64), 256>>>(0, eWih, ebih, NH3, NE);

    k_enc_persist<<<ENC_BLOCKS, 256>>>(eWhh, ebhh);

    k_sgemm64<<<dim3(NH / 64, (NB * NS) / 64), 256>>>(1, aW, ab, NH, NH);

    k_dec_init<<<NB, 256>>>(sd, emb);

    for (int d = 0; d < NT; d++) {
        k_dec_step<<<NH / 2, 128>>>(dWih, dWhh, dbih, dbhh, emb, d);
        k_fc_attn<<<64 + (NV + 127) / 128, 256>>>(fcb, out, d);
    }
}